// round 16
// baseline (speedup 1.0000x reference)
#include <cuda_runtime.h>
#include <cuda_fp16.h>
#include <math.h>
#include <stdint.h>

// ---------------- problem constants ----------------
#define BB   2
#define TT   2048
#define DM   512
#define NH   8
#define DH   64
#define DFF  2048
#define MM   (BB*TT)        // 4096 rows
#define CHK  64
#define NC   (TT/CHK)       // 32
#define BH   (BB*NH)        // 16
#define HRS  72             // fp16 smem row stride (elements)

// ---------------- scratch (device globals) ----------------
__device__ __align__(256) __half g_h1   [MM*DM];
__device__ __align__(256) __half g_q    [MM*DM];
__device__ __align__(256) __half g_k    [MM*DM];
__device__ __align__(256) __half g_v    [MM*DM];
__device__ __align__(256) __half g_attn1[MM*DM];
__device__ __align__(256) float  g_x2   [MM*DM];
__device__ __align__(256) __half g_h22  [MM*DM];
__device__ __align__(256) __half g_ffn1 [MM*DFF];
__device__ __align__(256) __half g_wqkv [3*DM*DM];
__device__ __align__(256) __half g_wo   [DM*DM];
__device__ __align__(256) __half g_w1   [DFF*DM];
__device__ __align__(256) __half g_w2   [DM*DFF];
__device__ __align__(256) __half g_ckv[BH*NC*DH*DH];
__device__ __align__(256) float  g_cz [BH*NC*DH];
__device__ __align__(256) __half g_Sp [BH*NC*DH*DH];
__device__ __align__(256) float  g_zp [BH*NC*DH];

// ---------------- helpers ----------------
__device__ __forceinline__ uint32_t smem_u32(const void* p){
    uint32_t a;
    asm("{ .reg .u64 t; cvta.to.shared.u64 t, %1; cvt.u32.u64 %0, t; }"
        : "=r"(a) : "l"(p));
    return a;
}
__device__ __forceinline__ void cp16(uint32_t dst, const void* src){
    asm volatile("cp.async.cg.shared.global [%0], [%1], 16;" :: "r"(dst), "l"(src));
}
__device__ __forceinline__ void cp_commit(){
    asm volatile("cp.async.commit_group;");
}
template<int N> __device__ __forceinline__ void cp_wait(){
    asm volatile("cp.async.wait_group %0;" :: "n"(N));
}
__device__ __forceinline__ void mma_f16(float* d, const uint32_t* a, const uint32_t* b){
    asm volatile(
        "mma.sync.aligned.m16n8k16.row.col.f32.f16.f16.f32 "
        "{%0,%1,%2,%3}, {%4,%5,%6,%7}, {%8,%9}, {%0,%1,%2,%3};"
        : "+f"(d[0]), "+f"(d[1]), "+f"(d[2]), "+f"(d[3])
        : "r"(a[0]), "r"(a[1]), "r"(a[2]), "r"(a[3]), "r"(b[0]), "r"(b[1]));
}
__device__ __forceinline__ void ldsm4(uint32_t& r0, uint32_t& r1, uint32_t& r2,
                                      uint32_t& r3, uint32_t addr){
    asm volatile("ldmatrix.sync.aligned.m8n8.x4.shared.b16 {%0,%1,%2,%3}, [%4];"
                 : "=r"(r0), "=r"(r1), "=r"(r2), "=r"(r3) : "r"(addr));
}
__device__ __forceinline__ uint32_t pack2h(__half a, __half b){
    return ((uint32_t)__half_as_ushort(b) << 16) | __half_as_ushort(a);
}

// ---------------- layernorm (fp32 in) -> fp16 out ----------------
__global__ __launch_bounds__(256) void lnh_kernel(
    const float* __restrict__ x, const float* __restrict__ g,
    const float* __restrict__ b, __half* __restrict__ o)
{
    int row = blockIdx.x;
    const float* xr = x + (size_t)row*DM;
    int tid = threadIdx.x;
    float v0 = xr[tid], v1 = xr[tid+256];
    float s = v0+v1, s2 = v0*v0+v1*v1;
#pragma unroll
    for (int off=16; off; off>>=1){
        s  += __shfl_xor_sync(0xffffffffu, s,  off);
        s2 += __shfl_xor_sync(0xffffffffu, s2, off);
    }
    __shared__ float rs[8], rs2[8], mu_s, rstd_s;
    if ((tid&31)==0){ rs[tid>>5]=s; rs2[tid>>5]=s2; }
    __syncthreads();
    if (tid==0){
        float a=0.f,c=0.f;
#pragma unroll
        for (int i=0;i<8;i++){ a+=rs[i]; c+=rs2[i]; }
        float mu = a*(1.0f/DM);
        float var = c*(1.0f/DM) - mu*mu;
        mu_s = mu; rstd_s = rsqrtf(var + 1e-5f);
    }
    __syncthreads();
    float mu = mu_s, rstd = rstd_s;
    __half* orow = o + (size_t)row*DM;
    orow[tid]     = __float2half_rn((v0-mu)*rstd*g[tid]     + b[tid]);
    orow[tid+256] = __float2half_rn((v1-mu)*rstd*g[tid+256] + b[tid+256]);
}

// ------ fused pre-kernel: blocks [0,4096) = LN1 rows; [4096,5632) = wconv ------
__global__ __launch_bounds__(256) void pre_kernel(
    const float* __restrict__ x, const float* __restrict__ ln1_g,
    const float* __restrict__ ln1_b, __half* __restrict__ h1,
    const float* __restrict__ Wq, const float* __restrict__ Wk,
    const float* __restrict__ Wv, const float* __restrict__ Wo,
    const float* __restrict__ W1, const float* __restrict__ W2,
    __half* __restrict__ wqkv, __half* __restrict__ wo,
    __half* __restrict__ w1,   __half* __restrict__ w2)
{
    int tid = threadIdx.x;
    if (blockIdx.x < MM){
        int row = blockIdx.x;
        const float* xr = x + (size_t)row*DM;
        float v0 = xr[tid], v1 = xr[tid+256];
        float s = v0+v1, s2 = v0*v0+v1*v1;
#pragma unroll
        for (int off=16; off; off>>=1){
            s  += __shfl_xor_sync(0xffffffffu, s,  off);
            s2 += __shfl_xor_sync(0xffffffffu, s2, off);
        }
        __shared__ float rs[8], rs2[8], mu_s, rstd_s;
        if ((tid&31)==0){ rs[tid>>5]=s; rs2[tid>>5]=s2; }
        __syncthreads();
        if (tid==0){
            float a=0.f,c=0.f;
#pragma unroll
            for (int i=0;i<8;i++){ a+=rs[i]; c+=rs2[i]; }
            float mu = a*(1.0f/DM);
            float var = c*(1.0f/DM) - mu*mu;
            mu_s = mu; rstd_s = rsqrtf(var + 1e-5f);
        }
        __syncthreads();
        float mu = mu_s, rstd = rstd_s;
        __half* orow = h1 + (size_t)row*DM;
        orow[tid]     = __float2half_rn((v0-mu)*rstd*ln1_g[tid]     + ln1_b[tid]);
        orow[tid+256] = __float2half_rn((v1-mu)*rstd*ln1_g[tid+256] + ln1_b[tid+256]);
    } else {
        int bid = blockIdx.x - MM;
        const float* W; __half* Bt;
        int Kd, Nd, nx, local;
        if (bid < 512){
            int seg = bid >> 7; local = bid & 127; nx = 16; Kd = 512; Nd = 512;
            W  = (seg==0)?Wq:(seg==1)?Wk:(seg==2)?Wv:Wo;
            Bt = (seg==0)?wqkv:(seg==1)?(wqkv+512*DM):(seg==2)?(wqkv+1024*DM):wo;
        } else if (bid < 1024){
            local = bid - 512; nx = 64; Kd = 512; Nd = 2048; W = W1; Bt = w1;
        } else {
            local = bid - 1024; nx = 16; Kd = 2048; Nd = 512; W = W2; Bt = w2;
        }
        int n0 = (local % nx)*32, k0 = (local / nx)*64;
        __shared__ float t[64][33];
        int tx = tid & 31, ty = tid >> 5;
#pragma unroll
        for (int i=ty;i<64;i+=8)
            t[i][tx] = W[(size_t)(k0+i)*Nd + n0 + tx];
        __syncthreads();
#pragma unroll
        for (int i=ty;i<32;i+=8){
            __half ha = __float2half_rn(t[2*tx][i]);
            __half hb = __float2half_rn(t[2*tx+1][i]);
            size_t base = (size_t)(n0+i)*Kd + k0 + 2*tx;
            *(uint32_t*)&Bt[base] = pack2h(ha, hb);
        }
    }
}

// ------- mma.sync fp16 GEMM, templated TN / pipeline depth, 2 CTAs/SM -------
// A[M,K], B[N,K].
// modes: 2 +bias0+res -> fp32 C0; 3 relu(+bias0) -> fp16 C3; 4 qkv split fp16 out
#define TM 128
#define RS 72
#define SMEM_MM 110592      // both variants use exactly this

template<int TNv, int NSTGv>
__global__ __launch_bounds__(256, 2) void mm_kernel(
    const __half* __restrict__ Ap, const __half* __restrict__ Bp,
    const float* __restrict__ bias0, const float* __restrict__ bias1,
    const float* __restrict__ bias2, const float* __restrict__ res,
    float* __restrict__ C0, __half* __restrict__ H0, __half* __restrict__ H1,
    __half* __restrict__ H2, __half* __restrict__ C3,
    int Np, int Kp, int mode)
{
    constexpr int ABYc = TM*RS*2;
    constexpr int BBYc = TNv*RS*2;
    constexpr int STGc = ABYc + BBYc;
    constexpr int NF   = TNv/16;      // n-fragments per warp
    constexpr int PR   = TNv/32;      // ldsm pair count for B
    extern __shared__ char smc[];
    uint32_t sb = smem_u32(smc);

    int tid = threadIdx.x;
    int lane = tid & 31, wid = tid >> 5;
    int wm = wid >> 1, wn = wid & 1;
    int g = lane >> 2, qp = lane & 3;
    int bm = blockIdx.y * TM;
    int bn = blockIdx.x * TNv;
    int nch = Kp >> 6;

    const char* Abase = (const char*)(Ap + (size_t)bm*Kp);
    const char* Bbase = (const char*)(Bp + (size_t)bn*Kp);
    const size_t rowb = (size_t)Kp*2;

    int lr_ = tid >> 3, lc_ = (tid & 7)*16;
    auto loadStage = [&](int c, int s){
        uint32_t da = sb + (uint32_t)s*STGc;
        uint32_t db = da + ABYc;
        const char* sa = Abase + (size_t)c*128 + (size_t)lr_*rowb + lc_;
        const char* sbp= Bbase + (size_t)c*128 + (size_t)lr_*rowb + lc_;
        uint32_t so = (uint32_t)(lr_*(RS*2) + lc_);
#pragma unroll
        for (int t=0;t<TM/32;t++)
            cp16(da + so + t*32*(RS*2), sa + (size_t)t*32*rowb);
#pragma unroll
        for (int t=0;t<TNv/32;t++)
            cp16(db + so + t*32*(RS*2), sbp + (size_t)t*32*rowb);
        cp_commit();
    };

    uint32_t a_off[2], b_off[PR];
#pragma unroll
    for (int mf=0; mf<2; mf++){
        int arow = wm*32 + mf*16 + (lane & 15);
        a_off[mf] = (uint32_t)(arow*(RS*2) + ((lane & 16) ? 16 : 0));
    }
#pragma unroll
    for (int p=0; p<PR; p++){
        int nrow = wn*(TNv/2) + p*16 + (lane & 7) + ((lane & 16) >> 1);
        b_off[p] = (uint32_t)(nrow*(RS*2) + ((lane & 8) ? 16 : 0)) + ABYc;
    }

    float acc[2][NF][4];
#pragma unroll
    for (int i=0;i<2;i++)
#pragma unroll
        for (int j=0;j<NF;j++)
#pragma unroll
            for (int k=0;k<4;k++) acc[i][j][k]=0.f;

#pragma unroll
    for (int s=0;s<NSTGv-1;s++) loadStage(s, s);

    int cur = 0, nxt = NSTGv-1;
    for (int i=0;i<nch;i++){
        cp_wait<NSTGv-2>();
        __syncthreads();
        if (i+NSTGv-1 < nch) loadStage(i+NSTGv-1, nxt);
        else cp_commit();
        uint32_t S = sb + (uint32_t)cur*STGc;
#pragma unroll
        for (int ks=0; ks<4; ks++){
            uint32_t koff = (uint32_t)(ks*32);
            uint32_t a[2][4];
            ldsm4(a[0][0],a[0][1],a[0][2],a[0][3], S + a_off[0] + koff);
            ldsm4(a[1][0],a[1][1],a[1][2],a[1][3], S + a_off[1] + koff);
            uint32_t b[NF][2];
#pragma unroll
            for (int p=0; p<PR; p++)
                ldsm4(b[2*p][0],b[2*p][1],b[2*p+1][0],b[2*p+1][1],
                      S + b_off[p] + koff);
#pragma unroll
            for (int mf=0; mf<2; mf++)
#pragma unroll
                for (int nf=0; nf<NF; nf++)
                    mma_f16(acc[mf][nf], a[mf], b[nf]);
        }
        cur = (cur==NSTGv-1) ? 0 : cur+1;
        nxt = (nxt==NSTGv-1) ? 0 : nxt+1;
    }

    // ---- epilogue ----
#pragma unroll
    for (int mf=0; mf<2; mf++){
#pragma unroll
        for (int half=0; half<2; half++){
            int m = bm + wm*32 + mf*16 + g + half*8;
#pragma unroll
            for (int nf=0; nf<NF; nf++){
                int n = bn + wn*(TNv/2) + nf*8 + qp*2;
                float v0 = acc[mf][nf][half*2+0];
                float v1 = acc[mf][nf][half*2+1];
                if (mode==2){
                    float2 rr = *(const float2*)&res[(size_t)m*Np + n];
                    v0 += bias0[n]   + rr.x;
                    v1 += bias0[n+1] + rr.y;
                    *(float2*)&C0[(size_t)m*Np + n] = make_float2(v0, v1);
                } else if (mode==4){
                    int sel = n >> 9;
                    int col = n & 511;
                    const float* bs = (sel==0) ? bias0 : (sel==1) ? bias1 : bias2;
                    v0 += bs[col]; v1 += bs[col+1];
                    if (sel < 2){
                        v0 = (v0 > 0.f) ? (v0+1.f) : expf(v0);
                        v1 = (v1 > 0.f) ? (v1+1.f) : expf(v1);
                    }
                    __half* Hs = (sel==0) ? H0 : (sel==1) ? H1 : H2;
                    *(uint32_t*)&Hs[(size_t)m*512 + col] =
                        pack2h(__float2half_rn(v0), __float2half_rn(v1));
                } else { // mode 3: relu -> fp16
                    v0 = fmaxf(v0 + bias0[n],   0.f);
                    v1 = fmaxf(v1 + bias0[n+1], 0.f);
                    *(uint32_t*)&C3[(size_t)m*Np + n] =
                        pack2h(__float2half_rn(v0), __float2half_rn(v1));
                }
            }
        }
    }
}

// ---------- per-chunk K^T V (fp16 out) and K sums via tensor cores ----------
__global__ __launch_bounds__(256, 4) void chunk_sums_kernel(
    const __half* __restrict__ Kf, const __half* __restrict__ Vf,
    __half* __restrict__ ckv, float* __restrict__ cz)
{
    __shared__ __half Kt[64*HRS];
    __shared__ __half Vt[64*HRS];
    int blk = blockIdx.x;
    int c = blk % NC, bh = blk / NC;
    int b = bh / NH, h = bh % NH;
    int t0 = c*CHK;
    int tid = threadIdx.x;
    int lr = tid >> 4, lc = (tid & 15)*4;
    for (int r = lr; r < 64; r += 16){
        size_t gi = ((size_t)(b*TT + t0 + r))*DM + h*DH + lc;
        uint2 kv = *(const uint2*)(Kf+gi);
        uint2 vv = *(const uint2*)(Vf+gi);
        const __half* kp = (const __half*)&kv;
        const __half* vp = (const __half*)&vv;
#pragma unroll
        for (int i=0;i<4;i++){
            Kt[(lc+i)*HRS + r] = kp[i];
            Vt[(lc+i)*HRS + r] = vp[i];
        }
    }
    __syncthreads();

    int lane = tid & 31, wid = tid >> 5;
    int mr = (wid & 3)*16, nb = (wid >> 2)*32;
    int g = lane >> 2, qp = lane & 3;
    uint32_t sbK = smem_u32(Kt), sbV = smem_u32(Vt);
    uint32_t aoff = sbK + (uint32_t)((mr + (lane & 15))*(HRS*2) + ((lane & 16) ? 16 : 0));
    uint32_t boff[2];
#pragma unroll
    for (int p=0;p<2;p++){
        int nrow = nb + p*16 + (lane & 7) + ((lane & 16) >> 1);
        boff[p] = sbV + (uint32_t)(nrow*(HRS*2) + ((lane & 8) ? 16 : 0));
    }
    float acc[4][4];
#pragma unroll
    for (int i=0;i<4;i++)
#pragma unroll
        for (int j=0;j<4;j++) acc[i][j]=0.f;
#pragma unroll
    for (int ks=0; ks<4; ks++){
        uint32_t koff = (uint32_t)(ks*32);
        uint32_t a[4];
        ldsm4(a[0],a[1],a[2],a[3], aoff + koff);
        uint32_t bfr[4][2];
#pragma unroll
        for (int p=0;p<2;p++)
            ldsm4(bfr[2*p][0],bfr[2*p][1],bfr[2*p+1][0],bfr[2*p+1][1],
                  boff[p] + koff);
#pragma unroll
        for (int nf=0;nf<4;nf++) mma_f16(acc[nf], a, bfr[nf]);
    }
    __half* outp = ckv + (size_t)blk*DH*DH;
#pragma unroll
    for (int nf=0;nf<4;nf++){
        int m = nb + nf*8 + qp*2;
        *(uint32_t*)&outp[(mr+g)*DH + m] =
            pack2h(__float2half_rn(acc[nf][0]), __float2half_rn(acc[nf][1]));
        *(uint32_t*)&outp[(mr+g+8)*DH + m] =
            pack2h(__float2half_rn(acc[nf][2]), __float2half_rn(acc[nf][3]));
    }
    if (tid < DH){
        float z = 0.f;
#pragma unroll 8
        for (int t=0;t<64;t++) z += __half2float(Kt[tid*HRS + t]);
        cz[(size_t)blk*DH + tid] = z;
    }
}

// --- parallel exclusive scan: 2 threads/element, fp16 in/out ---
__global__ __launch_bounds__(256) void scan_kernel(
    const __half* __restrict__ ckv, const float* __restrict__ cz,
    __half* __restrict__ Sp, float* __restrict__ zp)
{
    int bh  = blockIdx.x >> 5;
    int seg = blockIdx.x & 31;
    int tid = threadIdx.x;
    int e   = seg*128 + (tid & 127);
    int hf  = tid >> 7;
    size_t base = ((size_t)bh*NC)*(DH*DH) + e;
    const size_t cs = (size_t)DH*DH;

    float v[16];
#pragma unroll
    for (int c=0;c<16;c++) v[c] = __half2float(ckv[base + (size_t)c*cs]);
    if (hf == 0){
        float s = 0.f;
#pragma unroll
        for (int c=0;c<16;c++){
            Sp[base + (size_t)c*cs] = __float2half_rn(s);
            s += v[c];
        }
    } else {
        float s = 0.f;
#pragma unroll
        for (int c=0;c<16;c++) s += v[c];
        float v2[16];
#pragma unroll
        for (int c=0;c<16;c++) v2[c] = __half2float(ckv[base + (size_t)(16+c)*cs]);
#pragma unroll
        for (int c=0;c<16;c++){
            Sp[base + (size_t)(16+c)*cs] = __float2half_rn(s);
            s += v2[c];
        }
    }

    if (seg==0 && tid < DH){
        size_t zb = (size_t)bh*NC*DH + tid;
        float zv[NC];
#pragma unroll
        for (int c=0;c<NC;c++) zv[c] = cz[zb + (size_t)c*DH];
        float z = 0.f;
#pragma unroll
        for (int c=0;c<NC;c++){ zp[zb + (size_t)c*DH] = z; z += zv[c]; }
    }
}

// ---------- intra-chunk attention via tensor cores (3 CTAs/SM) ----------
__global__ __launch_bounds__(256, 3) void intra_kernel(
    const __half* __restrict__ Qf, const __half* __restrict__ Kf,
    const __half* __restrict__ Vf, const __half* __restrict__ Sp,
    const float* __restrict__ zp, __half* __restrict__ attn1)
{
    __shared__ __half Qs[64*HRS];   // [t][d]
    __shared__ __half Ks[64*HRS];   // [j][d]
    __shared__ __half Vt[64*HRS];   // [m][j]
    __shared__ __half St[64*HRS];   // [m][d]
    __shared__ __half Ss[64*HRS];   // [t][j]
    __shared__ float zs[64], dn[64], dnp[2][64];

    int blk = blockIdx.x;
    int c = blk % NC, bh = blk / NC;
    int b = bh / NH, h = bh % NH;
    int t0 = c*CHK;
    int tid = threadIdx.x;
    int lr = tid >> 4, lc = (tid & 15)*4;

    for (int r = lr; r < 64; r += 16){
        size_t gi = ((size_t)(b*TT + t0 + r))*DM + h*DH + lc;
        uint2 q = *(const uint2*)(Qf+gi);
        uint2 k = *(const uint2*)(Kf+gi);
        uint2 v = *(const uint2*)(Vf+gi);
        *(uint2*)&Qs[r*HRS + lc] = q;
        *(uint2*)&Ks[r*HRS + lc] = k;
        const __half* vp = (const __half*)&v;
#pragma unroll
        for (int i=0;i<4;i++) Vt[(lc+i)*HRS + r] = vp[i];
    }
    {
        size_t base = (size_t)blk*(DH*DH);
        for (int e = tid*4; e < DH*DH; e += 1024){
            uint2 sv = *(const uint2*)(Sp + base + e);
            const __half* sp = (const __half*)&sv;
            int d = e >> 6, m = e & 63;
            St[(m+0)*HRS + d] = sp[0];
            St[(m+1)*HRS + d] = sp[1];
            St[(m+2)*HRS + d] = sp[2];
            St[(m+3)*HRS + d] = sp[3];
        }
    }
    if (tid < DH) zs[tid] = zp[(size_t)blk*DH + tid];
    __syncthreads();

    int lane = tid & 31, wid = tid >> 5;
    int mr = (wid & 3)*16, nb = (wid >> 2)*32;
    int g = lane >> 2, qp = lane & 3;
    uint32_t sbQ = smem_u32(Qs), sbK = smem_u32(Ks);
    uint32_t sbV = smem_u32(Vt), sbSt = smem_u32(St), sbSs = smem_u32(Ss);

    uint32_t a_lane = (uint32_t)((mr + (lane & 15))*(HRS*2) + ((lane & 16) ? 16 : 0));
    uint32_t b_lane[2];
#pragma unroll
    for (int p=0;p<2;p++){
        int nrow = nb + p*16 + (lane & 7) + ((lane & 16) >> 1);
        b_lane[p] = (uint32_t)(nrow*(HRS*2) + ((lane & 8) ? 16 : 0));
    }

    // ---- GEMM1: S = Q K^T ----
    float acc[4][4];
#pragma unroll
    for (int i=0;i<4;i++)
#pragma unroll
        for (int j=0;j<4;j++) acc[i][j]=0.f;
#pragma unroll
    for (int ks=0; ks<4; ks++){
        uint32_t koff = (uint32_t)(ks*32);
        uint32_t a[4];
        ldsm4(a[0],a[1],a[2],a[3], sbQ + a_lane + koff);
        uint32_t bfr[4][2];
#pragma unroll
        for (int p=0;p<2;p++)
            ldsm4(bfr[2*p][0],bfr[2*p][1],bfr[2*p+1][0],bfr[2*p+1][1],
                  sbK + b_lane[p] + koff);
#pragma unroll
        for (int nf=0;nf<4;nf++) mma_f16(acc[nf], a, bfr[nf]);
    }

    // ---- mask, den partials, store Ss ----
    int r0 = mr + g, r1 = mr + g + 8;
    float slo = 0.f, shi = 0.f;
#pragma unroll
    for (int nf=0;nf<4;nf++){
        int col = nb + nf*8 + qp*2;
        float c0 = (col   <= r0) ? acc[nf][0] : 0.f;
        float c1 = (col+1 <= r0) ? acc[nf][1] : 0.f;
        float c2 = (col   <= r1) ? acc[nf][2] : 0.f;
        float c3 = (col+1 <= r1) ? acc[nf][3] : 0.f;
        slo += c0 + c1; shi += c2 + c3;
        *(uint32_t*)&Ss[r0*HRS + col] = pack2h(__float2half_rn(c0), __float2half_rn(c1));
        *(uint32_t*)&Ss[r1*HRS + col] = pack2h(__float2half_rn(c2), __float2half_rn(c3));
    }
    slo += __shfl_xor_sync(0xffffffffu, slo, 1);
    slo += __shfl_xor_sync(0xffffffffu, slo, 2);
    shi += __shfl_xor_sync(0xffffffffu, shi, 1);
    shi += __shfl_xor_sync(0xffffffffu, shi, 2);
    if (qp == 0){
        dnp[wid>>2][r0] = slo;
        dnp[wid>>2][r1] = shi;
    }
    __syncthreads();
    if (tid < 64){
        float dsum = dnp[0][tid] + dnp[1][tid];
#pragma unroll 8
        for (int d=0; d<64; d++)
            dsum += __half2float(Qs[tid*HRS + d]) * zs[d];
        dn[tid] = fmaxf(dsum, 1e-6f);
    }
    __syncthreads();

    // ---- GEMM2: num = Ss@Vt + Qs@St ----
    float acc2[4][4];
#pragma unroll
    for (int i=0;i<4;i++)
#pragma unroll
        for (int j=0;j<4;j++) acc2[i][j]=0.f;
#pragma unroll
    for (int ks=0; ks<4; ks++){
        uint32_t koff = (uint32_t)(ks*32);
        uint32_t a[4];
        ldsm4(a[0],a[1],a[2],a[3], sbSs + a_lane + koff);
        uint32_t bfr[4][2];
#pragma unroll
        for (int p=0;p<2;p++)
            ldsm4(bfr[2*p][0],bfr[2*p][1],bfr[2*p+1][0],bfr[2*p+1][1],
                  sbV + b_lane[p] + koff);
#pragma unroll
        for (int nf=0;nf<4;nf++) mma_f16(acc2[nf], a, bfr[nf]);
    }
#pragma unroll
    for (int ks=0; ks<4; ks++){
        uint32_t koff = (uint32_t)(ks*32);
        uint32_t a[4];
        ldsm4(a[0],a[1],a[2],a[3], sbQ + a_lane + koff);
        uint32_t bfr[4][2];
#pragma unroll
        for (int p=0;p<2;p++)
            ldsm4(bfr[2*p][0],bfr[2*p][1],bfr[2*p+1][0],bfr[2*p+1][1],
                  sbSt + b_lane[p] + koff);
#pragma unroll
        for (int nf=0;nf<4;nf++) mma_f16(acc2[nf], a, bfr[nf]);
    }

    float inv0 = 1.0f / dn[r0];
    float inv1 = 1.0f / dn[r1];
#pragma unroll
    for (int nf=0;nf<4;nf++){
        int col = nb + nf*8 + qp*2;
        size_t g0 = ((size_t)(b*TT + t0 + r0))*DM + h*DH + col;
        size_t g1 = ((size_t)(b*TT + t0 + r1))*DM + h*DH + col;
        *(uint32_t*)&attn1[g0] = pack2h(__float2half_rn(acc2[nf][0]*inv0),
                                        __float2half_rn(acc2[nf][1]*inv0));
        *(uint32_t*)&attn1[g1] = pack2h(__float2half_rn(acc2[nf][2]*inv1),
                                        __float2half_rn(acc2[nf][3]*inv1));
    }
}

// ---------------- launch ----------------
extern "C" void kernel_launch(void* const* d_in, const int* in_sizes, int n_in,
                              void* d_out, int out_size)
{
    (void)in_sizes; (void)n_in; (void)out_size;
    const float* x     = (const float*)d_in[0];
    const float* ln1_g = (const float*)d_in[1];
    const float* ln1_b = (const float*)d_in[2];
    const float* Wq    = (const float*)d_in[3];
    const float* bq    = (const float*)d_in[4];
    const float* Wk    = (const float*)d_in[5];
    const float* bk    = (const float*)d_in[6];
    const float* Wv    = (const float*)d_in[7];
    const float* bv    = (const float*)d_in[8];
    const float* Wo    = (const float*)d_in[9];
    const float* bo    = (const float*)d_in[10];
    const float* ln2_g = (const float*)d_in[11];
    const float* ln2_b = (const float*)d_in[12];
    const float* W1    = (const float*)d_in[13];
    const float* b1    = (const float*)d_in[14];
    const float* W2    = (const float*)d_in[15];
    const float* b2    = (const float*)d_in[16];
    float* out = (float*)d_out;

    static bool attr_done = false;
    if (!attr_done){
        cudaFuncSetAttribute(mm_kernel<128,3>,
                             cudaFuncAttributeMaxDynamicSharedMemorySize, SMEM_MM);
        cudaFuncSetAttribute(mm_kernel<64,4>,
                             cudaFuncAttributeMaxDynamicSharedMemorySize, SMEM_MM);
        attr_done = true;
    }

    __half *h1b,*attn1b,*h22b,*ffn1b,*wqkvb,*wob,*w1b,*w2b,*qb,*kb,*vb,*Spb,*ckvb;
    float *x2b,*czb,*zpb;
    cudaGetSymbolAddress((void**)&h1b,   g_h1);
    cudaGetSymbolAddress((void**)&qb,    g_q);
    cudaGetSymbolAddress((void**)&kb,    g_k);
    cudaGetSymbolAddress((void**)&vb,    g_v);
    cudaGetSymbolAddress((void**)&attn1b,g_attn1);
    cudaGetSymbolAddress((void**)&x2b,   g_x2);
    cudaGetSymbolAddress((void**)&h22b,  g_h22);
    cudaGetSymbolAddress((void**)&ffn1b, g_ffn1);
    cudaGetSymbolAddress((void**)&wqkvb, g_wqkv);
    cudaGetSymbolAddress((void**)&wob,   g_wo);
    cudaGetSymbolAddress((void**)&w1b,   g_w1);
    cudaGetSymbolAddress((void**)&w2b,   g_w2);
    cudaGetSymbolAddress((void**)&ckvb,  g_ckv);
    cudaGetSymbolAddress((void**)&czb,   g_cz);
    cudaGetSymbolAddress((void**)&Spb,   g_Sp);
    cudaGetSymbolAddress((void**)&zpb,   g_zp);

    dim3 gQKV(3*DM/128, MM/TM);     // (12, 32) TN=128
    dim3 gFF(DFF/128, MM/TM);       // (16, 32) TN=128
    dim3 gDM64(DM/64, MM/TM);       // (8, 32)  TN=64  -> 256 CTAs

    // sublayer 1 (LN1 + weight conversion fused into one launch)
    pre_kernel<<<MM + 1536, 256>>>(x, ln1_g, ln1_b, h1b,
                                   Wq, Wk, Wv, Wo, W1, W2,
                                   wqkvb, wob, w1b, w2b);
    mm_kernel<128,3><<<gQKV, 256, SMEM_MM>>>(h1b, wqkvb, bq, bk, bv, nullptr,
                                             nullptr, qb, kb, vb, nullptr,
                                             DM, DM, 4);
    chunk_sums_kernel<<<BH*NC, 256>>>(kb, vb, ckvb, czb);
    scan_kernel<<<BH*32, 256>>>(ckvb, czb, Spb, zpb);
    intra_kernel<<<BH*NC, 256>>>(qb, kb, vb, Spb, zpb, attn1b);
    mm_kernel<64,4><<<gDM64, 256, SMEM_MM>>>(attn1b, wob, bo, nullptr, nullptr, x,
                                             x2b, nullptr, nullptr, nullptr, nullptr,
                                             DM, DM, 2);
    lnh_kernel<<<MM, 256>>>(x2b, ln2_g, ln2_b, h22b);

    // sublayer 2
    mm_kernel<128,3><<<gFF, 256, SMEM_MM>>>(h22b, w1b, b1, nullptr, nullptr, nullptr,
                                            nullptr, nullptr, nullptr, nullptr, ffn1b,
                                            DFF, DM, 3);
    mm_kernel<64,4><<<gDM64, 256, SMEM_MM>>>(ffn1b, w2b, b2, nullptr, nullptr, x2b,
                                             out, nullptr, nullptr, nullptr, nullptr,
                                             DM, DFF, 2);
}

// round 17
// speedup vs baseline: 1.0288x; 1.0288x over previous
#include <cuda_runtime.h>
#include <cuda_fp16.h>
#include <math.h>
#include <stdint.h>

// ---------------- problem constants ----------------
#define BB   2
#define TT   2048
#define DM   512
#define NH   8
#define DH   64
#define DFF  2048
#define MM   (BB*TT)        // 4096 rows
#define CHK  64
#define NC   (TT/CHK)       // 32
#define BH   (BB*NH)        // 16
#define HRS  72             // fp16 smem row stride (elements)

// ---------------- scratch (device globals) ----------------
__device__ __align__(256) __half g_h1   [MM*DM];
__device__ __align__(256) __half g_q    [MM*DM];
__device__ __align__(256) __half g_k    [MM*DM];
__device__ __align__(256) __half g_v    [MM*DM];
__device__ __align__(256) __half g_attn1[MM*DM];
__device__ __align__(256) float  g_x2   [MM*DM];
__device__ __align__(256) __half g_h22  [MM*DM];
__device__ __align__(256) __half g_ffn1 [MM*DFF];
__device__ __align__(256) __half g_wqkv [3*DM*DM];
__device__ __align__(256) __half g_wo   [DM*DM];
__device__ __align__(256) __half g_w1   [DFF*DM];
__device__ __align__(256) __half g_w2   [DM*DFF];
__device__ __align__(256) __half g_ckv[BH*NC*DH*DH];
__device__ __align__(256) float  g_cz [BH*NC*DH];
__device__ __align__(256) __half g_Sp [BH*NC*DH*DH];
__device__ __align__(256) float  g_zp [BH*NC*DH];

// ---------------- helpers ----------------
__device__ __forceinline__ uint32_t smem_u32(const void* p){
    uint32_t a;
    asm("{ .reg .u64 t; cvta.to.shared.u64 t, %1; cvt.u32.u64 %0, t; }"
        : "=r"(a) : "l"(p));
    return a;
}
__device__ __forceinline__ void cp16(uint32_t dst, const void* src){
    asm volatile("cp.async.cg.shared.global [%0], [%1], 16;" :: "r"(dst), "l"(src));
}
__device__ __forceinline__ void cp_commit(){
    asm volatile("cp.async.commit_group;");
}
template<int N> __device__ __forceinline__ void cp_wait(){
    asm volatile("cp.async.wait_group %0;" :: "n"(N));
}
__device__ __forceinline__ void mma_f16(float* d, const uint32_t* a, const uint32_t* b){
    asm volatile(
        "mma.sync.aligned.m16n8k16.row.col.f32.f16.f16.f32 "
        "{%0,%1,%2,%3}, {%4,%5,%6,%7}, {%8,%9}, {%0,%1,%2,%3};"
        : "+f"(d[0]), "+f"(d[1]), "+f"(d[2]), "+f"(d[3])
        : "r"(a[0]), "r"(a[1]), "r"(a[2]), "r"(a[3]), "r"(b[0]), "r"(b[1]));
}
__device__ __forceinline__ void ldsm4(uint32_t& r0, uint32_t& r1, uint32_t& r2,
                                      uint32_t& r3, uint32_t addr){
    asm volatile("ldmatrix.sync.aligned.m8n8.x4.shared.b16 {%0,%1,%2,%3}, [%4];"
                 : "=r"(r0), "=r"(r1), "=r"(r2), "=r"(r3) : "r"(addr));
}
__device__ __forceinline__ uint32_t pack2h(__half a, __half b){
    return ((uint32_t)__half_as_ushort(b) << 16) | __half_as_ushort(a);
}

// ---------------- layernorm (fp32 in) -> fp16 out ----------------
__global__ __launch_bounds__(256) void lnh_kernel(
    const float* __restrict__ x, const float* __restrict__ g,
    const float* __restrict__ b, __half* __restrict__ o)
{
    int row = blockIdx.x;
    const float* xr = x + (size_t)row*DM;
    int tid = threadIdx.x;
    float v0 = xr[tid], v1 = xr[tid+256];
    float s = v0+v1, s2 = v0*v0+v1*v1;
#pragma unroll
    for (int off=16; off; off>>=1){
        s  += __shfl_xor_sync(0xffffffffu, s,  off);
        s2 += __shfl_xor_sync(0xffffffffu, s2, off);
    }
    __shared__ float rs[8], rs2[8], mu_s, rstd_s;
    if ((tid&31)==0){ rs[tid>>5]=s; rs2[tid>>5]=s2; }
    __syncthreads();
    if (tid==0){
        float a=0.f,c=0.f;
#pragma unroll
        for (int i=0;i<8;i++){ a+=rs[i]; c+=rs2[i]; }
        float mu = a*(1.0f/DM);
        float var = c*(1.0f/DM) - mu*mu;
        mu_s = mu; rstd_s = rsqrtf(var + 1e-5f);
    }
    __syncthreads();
    float mu = mu_s, rstd = rstd_s;
    __half* orow = o + (size_t)row*DM;
    orow[tid]     = __float2half_rn((v0-mu)*rstd*g[tid]     + b[tid]);
    orow[tid+256] = __float2half_rn((v1-mu)*rstd*g[tid+256] + b[tid+256]);
}

// ------ fused pre-kernel: blocks [0,4096) = LN1 rows; [4096,5632) = wconv ------
__global__ __launch_bounds__(256) void pre_kernel(
    const float* __restrict__ x, const float* __restrict__ ln1_g,
    const float* __restrict__ ln1_b, __half* __restrict__ h1,
    const float* __restrict__ Wq, const float* __restrict__ Wk,
    const float* __restrict__ Wv, const float* __restrict__ Wo,
    const float* __restrict__ W1, const float* __restrict__ W2,
    __half* __restrict__ wqkv, __half* __restrict__ wo,
    __half* __restrict__ w1,   __half* __restrict__ w2)
{
    int tid = threadIdx.x;
    if (blockIdx.x < MM){
        int row = blockIdx.x;
        const float* xr = x + (size_t)row*DM;
        float v0 = xr[tid], v1 = xr[tid+256];
        float s = v0+v1, s2 = v0*v0+v1*v1;
#pragma unroll
        for (int off=16; off; off>>=1){
            s  += __shfl_xor_sync(0xffffffffu, s,  off);
            s2 += __shfl_xor_sync(0xffffffffu, s2, off);
        }
        __shared__ float rs[8], rs2[8], mu_s, rstd_s;
        if ((tid&31)==0){ rs[tid>>5]=s; rs2[tid>>5]=s2; }
        __syncthreads();
        if (tid==0){
            float a=0.f,c=0.f;
#pragma unroll
            for (int i=0;i<8;i++){ a+=rs[i]; c+=rs2[i]; }
            float mu = a*(1.0f/DM);
            float var = c*(1.0f/DM) - mu*mu;
            mu_s = mu; rstd_s = rsqrtf(var + 1e-5f);
        }
        __syncthreads();
        float mu = mu_s, rstd = rstd_s;
        __half* orow = h1 + (size_t)row*DM;
        orow[tid]     = __float2half_rn((v0-mu)*rstd*ln1_g[tid]     + ln1_b[tid]);
        orow[tid+256] = __float2half_rn((v1-mu)*rstd*ln1_g[tid+256] + ln1_b[tid+256]);
    } else {
        int bid = blockIdx.x - MM;
        const float* W; __half* Bt;
        int Kd, Nd, nx, local;
        if (bid < 512){
            int seg = bid >> 7; local = bid & 127; nx = 16; Kd = 512; Nd = 512;
            W  = (seg==0)?Wq:(seg==1)?Wk:(seg==2)?Wv:Wo;
            Bt = (seg==0)?wqkv:(seg==1)?(wqkv+512*DM):(seg==2)?(wqkv+1024*DM):wo;
        } else if (bid < 1024){
            local = bid - 512; nx = 64; Kd = 512; Nd = 2048; W = W1; Bt = w1;
        } else {
            local = bid - 1024; nx = 16; Kd = 2048; Nd = 512; W = W2; Bt = w2;
        }
        int n0 = (local % nx)*32, k0 = (local / nx)*64;
        __shared__ float t[64][33];
        int tx = tid & 31, ty = tid >> 5;
#pragma unroll
        for (int i=ty;i<64;i+=8)
            t[i][tx] = W[(size_t)(k0+i)*Nd + n0 + tx];
        __syncthreads();
#pragma unroll
        for (int i=ty;i<32;i+=8){
            __half ha = __float2half_rn(t[2*tx][i]);
            __half hb = __float2half_rn(t[2*tx+1][i]);
            size_t base = (size_t)(n0+i)*Kd + k0 + 2*tx;
            *(uint32_t*)&Bt[base] = pack2h(ha, hb);
        }
    }
}

// ------------- mma.sync fp16 GEMM, 3-stage pipeline, 2 CTAs/SM -------------
// A[M,K], B[N,K]. tile 128x128.
// modes: 2 +bias0+res -> fp32 C0; 3 relu(+bias0) -> fp16 C3; 4 qkv split fp16 out
#define TM 128
#define TN 128
#define RS 72
#define ABY (TM*RS*2)
#define STGB (2*ABY)
#define NSTG 3
#define SMEM_MM (NSTG*STGB)

__global__ __launch_bounds__(256, 2) void mm_kernel(
    const __half* __restrict__ Ap, const __half* __restrict__ Bp,
    const float* __restrict__ bias0, const float* __restrict__ bias1,
    const float* __restrict__ bias2, const float* __restrict__ res,
    float* __restrict__ C0, __half* __restrict__ H0, __half* __restrict__ H1,
    __half* __restrict__ H2, __half* __restrict__ C3,
    int Np, int Kp, int mode)
{
    extern __shared__ char smc[];
    uint32_t sb = smem_u32(smc);

    int tid = threadIdx.x;
    int lane = tid & 31, wid = tid >> 5;
    int wm = wid >> 1, wn = wid & 1;
    int g = lane >> 2, qp = lane & 3;
    int bm = blockIdx.y * TM;
    int bn = blockIdx.x * TN;
    int nch = Kp >> 6;

    const char* Abase = (const char*)(Ap + (size_t)bm*Kp);
    const char* Bbase = (const char*)(Bp + (size_t)bn*Kp);
    const size_t rowb = (size_t)Kp*2;

    int lr_ = tid >> 3, lc_ = (tid & 7)*16;
    auto loadStage = [&](int c, int s){
        uint32_t da = sb + (uint32_t)s*STGB;
        uint32_t db = da + ABY;
        const char* sa = Abase + (size_t)c*128 + (size_t)lr_*rowb + lc_;
        const char* sbp= Bbase + (size_t)c*128 + (size_t)lr_*rowb + lc_;
        uint32_t so = (uint32_t)(lr_*(RS*2) + lc_);
#pragma unroll
        for (int t=0;t<4;t++){
            cp16(da + so + t*32*(RS*2), sa + (size_t)t*32*rowb);
            cp16(db + so + t*32*(RS*2), sbp + (size_t)t*32*rowb);
        }
        cp_commit();
    };

    uint32_t a_off[2], b_off[4];
#pragma unroll
    for (int mf=0; mf<2; mf++){
        int arow = wm*32 + mf*16 + (lane & 15);
        a_off[mf] = (uint32_t)(arow*(RS*2) + ((lane & 16) ? 16 : 0));
    }
#pragma unroll
    for (int p=0; p<4; p++){
        int nrow = wn*64 + p*16 + (lane & 7) + ((lane & 16) >> 1);
        b_off[p] = (uint32_t)(nrow*(RS*2) + ((lane & 8) ? 16 : 0)) + ABY;
    }

    float acc[2][8][4];
#pragma unroll
    for (int i=0;i<2;i++)
#pragma unroll
        for (int j=0;j<8;j++)
#pragma unroll
            for (int k=0;k<4;k++) acc[i][j][k]=0.f;

    loadStage(0,0); loadStage(1,1);

    int cur = 0, nxt = 2;
    for (int i=0;i<nch;i++){
        cp_wait<NSTG-2>();
        __syncthreads();
        if (i+2 < nch) loadStage(i+2, nxt);
        else cp_commit();
        uint32_t S = sb + (uint32_t)cur*STGB;
#pragma unroll
        for (int ks=0; ks<4; ks++){
            uint32_t koff = (uint32_t)(ks*32);
            uint32_t a[2][4];
            ldsm4(a[0][0],a[0][1],a[0][2],a[0][3], S + a_off[0] + koff);
            ldsm4(a[1][0],a[1][1],a[1][2],a[1][3], S + a_off[1] + koff);
            uint32_t b[8][2];
#pragma unroll
            for (int p=0; p<4; p++)
                ldsm4(b[2*p][0],b[2*p][1],b[2*p+1][0],b[2*p+1][1],
                      S + b_off[p] + koff);
#pragma unroll
            for (int mf=0; mf<2; mf++)
#pragma unroll
                for (int nf=0; nf<8; nf++)
                    mma_f16(acc[mf][nf], a[mf], b[nf]);
        }
        cur = (cur==NSTG-1) ? 0 : cur+1;
        nxt = (nxt==NSTG-1) ? 0 : nxt+1;
    }

    // ---- epilogue ----
#pragma unroll
    for (int mf=0; mf<2; mf++){
#pragma unroll
        for (int half=0; half<2; half++){
            int m = bm + wm*32 + mf*16 + g + half*8;
#pragma unroll
            for (int nf=0; nf<8; nf++){
                int n = bn + wn*64 + nf*8 + qp*2;
                float v0 = acc[mf][nf][half*2+0];
                float v1 = acc[mf][nf][half*2+1];
                if (mode==2){
                    float2 rr = *(const float2*)&res[(size_t)m*Np + n];
                    v0 += bias0[n]   + rr.x;
                    v1 += bias0[n+1] + rr.y;
                    *(float2*)&C0[(size_t)m*Np + n] = make_float2(v0, v1);
                } else if (mode==4){
                    int sel = n >> 9;
                    int col = n & 511;
                    const float* bs = (sel==0) ? bias0 : (sel==1) ? bias1 : bias2;
                    v0 += bs[col]; v1 += bs[col+1];
                    if (sel < 2){
                        v0 = (v0 > 0.f) ? (v0+1.f) : expf(v0);
                        v1 = (v1 > 0.f) ? (v1+1.f) : expf(v1);
                    }
                    __half* Hs = (sel==0) ? H0 : (sel==1) ? H1 : H2;
                    *(uint32_t*)&Hs[(size_t)m*512 + col] =
                        pack2h(__float2half_rn(v0), __float2half_rn(v1));
                } else { // mode 3: relu -> fp16
                    v0 = fmaxf(v0 + bias0[n],   0.f);
                    v1 = fmaxf(v1 + bias0[n+1], 0.f);
                    *(uint32_t*)&C3[(size_t)m*Np + n] =
                        pack2h(__float2half_rn(v0), __float2half_rn(v1));
                }
            }
        }
    }
}

// ---------- per-chunk K^T V (fp16 out) and K sums via tensor cores ----------
__global__ __launch_bounds__(256, 4) void chunk_sums_kernel(
    const __half* __restrict__ Kf, const __half* __restrict__ Vf,
    __half* __restrict__ ckv, float* __restrict__ cz)
{
    __shared__ __half Kt[64*HRS];
    __shared__ __half Vt[64*HRS];
    int blk = blockIdx.x;
    int c = blk % NC, bh = blk / NC;
    int b = bh / NH, h = bh % NH;
    int t0 = c*CHK;
    int tid = threadIdx.x;
    int lr = tid >> 4, lc = (tid & 15)*4;
    for (int r = lr; r < 64; r += 16){
        size_t gi = ((size_t)(b*TT + t0 + r))*DM + h*DH + lc;
        uint2 kv = *(const uint2*)(Kf+gi);
        uint2 vv = *(const uint2*)(Vf+gi);
        const __half* kp = (const __half*)&kv;
        const __half* vp = (const __half*)&vv;
#pragma unroll
        for (int i=0;i<4;i++){
            Kt[(lc+i)*HRS + r] = kp[i];
            Vt[(lc+i)*HRS + r] = vp[i];
        }
    }
    __syncthreads();

    int lane = tid & 31, wid = tid >> 5;
    int mr = (wid & 3)*16, nb = (wid >> 2)*32;
    int g = lane >> 2, qp = lane & 3;
    uint32_t sbK = smem_u32(Kt), sbV = smem_u32(Vt);
    uint32_t aoff = sbK + (uint32_t)((mr + (lane & 15))*(HRS*2) + ((lane & 16) ? 16 : 0));
    uint32_t boff[2];
#pragma unroll
    for (int p=0;p<2;p++){
        int nrow = nb + p*16 + (lane & 7) + ((lane & 16) >> 1);
        boff[p] = sbV + (uint32_t)(nrow*(HRS*2) + ((lane & 8) ? 16 : 0));
    }
    float acc[4][4];
#pragma unroll
    for (int i=0;i<4;i++)
#pragma unroll
        for (int j=0;j<4;j++) acc[i][j]=0.f;
#pragma unroll
    for (int ks=0; ks<4; ks++){
        uint32_t koff = (uint32_t)(ks*32);
        uint32_t a[4];
        ldsm4(a[0],a[1],a[2],a[3], aoff + koff);
        uint32_t bfr[4][2];
#pragma unroll
        for (int p=0;p<2;p++)
            ldsm4(bfr[2*p][0],bfr[2*p][1],bfr[2*p+1][0],bfr[2*p+1][1],
                  boff[p] + koff);
#pragma unroll
        for (int nf=0;nf<4;nf++) mma_f16(acc[nf], a, bfr[nf]);
    }
    __half* outp = ckv + (size_t)blk*DH*DH;
#pragma unroll
    for (int nf=0;nf<4;nf++){
        int m = nb + nf*8 + qp*2;
        *(uint32_t*)&outp[(mr+g)*DH + m] =
            pack2h(__float2half_rn(acc[nf][0]), __float2half_rn(acc[nf][1]));
        *(uint32_t*)&outp[(mr+g+8)*DH + m] =
            pack2h(__float2half_rn(acc[nf][2]), __float2half_rn(acc[nf][3]));
    }
    if (tid < DH){
        float z = 0.f;
#pragma unroll 8
        for (int t=0;t<64;t++) z += __half2float(Kt[tid*HRS + t]);
        cz[(size_t)blk*DH + tid] = z;
    }
}

// --- parallel exclusive scan: 2 threads/element, fp16 in/out ---
__global__ __launch_bounds__(256) void scan_kernel(
    const __half* __restrict__ ckv, const float* __restrict__ cz,
    __half* __restrict__ Sp, float* __restrict__ zp)
{
    int bh  = blockIdx.x >> 5;
    int seg = blockIdx.x & 31;
    int tid = threadIdx.x;
    int e   = seg*128 + (tid & 127);
    int hf  = tid >> 7;
    size_t base = ((size_t)bh*NC)*(DH*DH) + e;
    const size_t cs = (size_t)DH*DH;

    float v[16];
#pragma unroll
    for (int c=0;c<16;c++) v[c] = __half2float(ckv[base + (size_t)c*cs]);
    if (hf == 0){
        float s = 0.f;
#pragma unroll
        for (int c=0;c<16;c++){
            Sp[base + (size_t)c*cs] = __float2half_rn(s);
            s += v[c];
        }
    } else {
        float s = 0.f;
#pragma unroll
        for (int c=0;c<16;c++) s += v[c];
        float v2[16];
#pragma unroll
        for (int c=0;c<16;c++) v2[c] = __half2float(ckv[base + (size_t)(16+c)*cs]);
#pragma unroll
        for (int c=0;c<16;c++){
            Sp[base + (size_t)(16+c)*cs] = __float2half_rn(s);
            s += v2[c];
        }
    }

    if (seg==0 && tid < DH){
        size_t zb = (size_t)bh*NC*DH + tid;
        float zv[NC];
#pragma unroll
        for (int c=0;c<NC;c++) zv[c] = cz[zb + (size_t)c*DH];
        float z = 0.f;
#pragma unroll
        for (int c=0;c<NC;c++){ zp[zb + (size_t)c*DH] = z; z += zv[c]; }
    }
}

// ---------- intra-chunk attention via tensor cores (3 CTAs/SM) ----------
__global__ __launch_bounds__(256, 3) void intra_kernel(
    const __half* __restrict__ Qf, const __half* __restrict__ Kf,
    const __half* __restrict__ Vf, const __half* __restrict__ Sp,
    const float* __restrict__ zp, __half* __restrict__ attn1)
{
    __shared__ __half Qs[64*HRS];   // [t][d]
    __shared__ __half Ks[64*HRS];   // [j][d]
    __shared__ __half Vt[64*HRS];   // [m][j]
    __shared__ __half St[64*HRS];   // [m][d]
    __shared__ __half Ss[64*HRS];   // [t][j]
    __shared__ float zs[64], dn[64], dnp[2][64];

    int blk = blockIdx.x;
    int c = blk % NC, bh = blk / NC;
    int b = bh / NH, h = bh % NH;
    int t0 = c*CHK;
    int tid = threadIdx.x;
    int lr = tid >> 4, lc = (tid & 15)*4;

    for (int r = lr; r < 64; r += 16){
        size_t gi = ((size_t)(b*TT + t0 + r))*DM + h*DH + lc;
        uint2 q = *(const uint2*)(Qf+gi);
        uint2 k = *(const uint2*)(Kf+gi);
        uint2 v = *(const uint2*)(Vf+gi);
        *(uint2*)&Qs[r*HRS + lc] = q;
        *(uint2*)&Ks[r*HRS + lc] = k;
        const __half* vp = (const __half*)&v;
#pragma unroll
        for (int i=0;i<4;i++) Vt[(lc+i)*HRS + r] = vp[i];
    }
    {
        size_t base = (size_t)blk*(DH*DH);
        for (int e = tid*4; e < DH*DH; e += 1024){
            uint2 sv = *(const uint2*)(Sp + base + e);
            const __half* sp = (const __half*)&sv;
            int d = e >> 6, m = e & 63;
            St[(m+0)*HRS + d] = sp[0];
            St[(m+1)*HRS + d] = sp[1];
            St[(m+2)*HRS + d] = sp[2];
            St[(m+3)*HRS + d] = sp[3];
        }
    }
    if (tid < DH) zs[tid] = zp[(size_t)blk*DH + tid];
    __syncthreads();

    int lane = tid & 31, wid = tid >> 5;
    int mr = (wid & 3)*16, nb = (wid >> 2)*32;
    int g = lane >> 2, qp = lane & 3;
    uint32_t sbQ = smem_u32(Qs), sbK = smem_u32(Ks);
    uint32_t sbV = smem_u32(Vt), sbSt = smem_u32(St), sbSs = smem_u32(Ss);

    uint32_t a_lane = (uint32_t)((mr + (lane & 15))*(HRS*2) + ((lane & 16) ? 16 : 0));
    uint32_t b_lane[2];
#pragma unroll
    for (int p=0;p<2;p++){
        int nrow = nb + p*16 + (lane & 7) + ((lane & 16) >> 1);
        b_lane[p] = (uint32_t)(nrow*(HRS*2) + ((lane & 8) ? 16 : 0));
    }

    // ---- GEMM1: S = Q K^T ----
    float acc[4][4];
#pragma unroll
    for (int i=0;i<4;i++)
#pragma unroll
        for (int j=0;j<4;j++) acc[i][j]=0.f;
#pragma unroll
    for (int ks=0; ks<4; ks++){
        uint32_t koff = (uint32_t)(ks*32);
        uint32_t a[4];
        ldsm4(a[0],a[1],a[2],a[3], sbQ + a_lane + koff);
        uint32_t bfr[4][2];
#pragma unroll
        for (int p=0;p<2;p++)
            ldsm4(bfr[2*p][0],bfr[2*p][1],bfr[2*p+1][0],bfr[2*p+1][1],
                  sbK + b_lane[p] + koff);
#pragma unroll
        for (int nf=0;nf<4;nf++) mma_f16(acc[nf], a, bfr[nf]);
    }

    // ---- mask, den partials, store Ss ----
    int r0 = mr + g, r1 = mr + g + 8;
    float slo = 0.f, shi = 0.f;
#pragma unroll
    for (int nf=0;nf<4;nf++){
        int col = nb + nf*8 + qp*2;
        float c0 = (col   <= r0) ? acc[nf][0] : 0.f;
        float c1 = (col+1 <= r0) ? acc[nf][1] : 0.f;
        float c2 = (col   <= r1) ? acc[nf][2] : 0.f;
        float c3 = (col+1 <= r1) ? acc[nf][3] : 0.f;
        slo += c0 + c1; shi += c2 + c3;
        *(uint32_t*)&Ss[r0*HRS + col] = pack2h(__float2half_rn(c0), __float2half_rn(c1));
        *(uint32_t*)&Ss[r1*HRS + col] = pack2h(__float2half_rn(c2), __float2half_rn(c3));
    }
    slo += __shfl_xor_sync(0xffffffffu, slo, 1);
    slo += __shfl_xor_sync(0xffffffffu, slo, 2);
    shi += __shfl_xor_sync(0xffffffffu, shi, 1);
    shi += __shfl_xor_sync(0xffffffffu, shi, 2);
    if (qp == 0){
        dnp[wid>>2][r0] = slo;
        dnp[wid>>2][r1] = shi;
    }
    __syncthreads();
    if (tid < 64){
        float dsum = dnp[0][tid] + dnp[1][tid];
#pragma unroll 8
        for (int d=0; d<64; d++)
            dsum += __half2float(Qs[tid*HRS + d]) * zs[d];
        dn[tid] = fmaxf(dsum, 1e-6f);
    }
    __syncthreads();

    // ---- GEMM2: num = Ss@Vt + Qs@St ----
    float acc2[4][4];
#pragma unroll
    for (int i=0;i<4;i++)
#pragma unroll
        for (int j=0;j<4;j++) acc2[i][j]=0.f;
#pragma unroll
    for (int ks=0; ks<4; ks++){
        uint32_t koff = (uint32_t)(ks*32);
        uint32_t a[4];
        ldsm4(a[0],a[1],a[2],a[3], sbSs + a_lane + koff);
        uint32_t bfr[4][2];
#pragma unroll
        for (int p=0;p<2;p++)
            ldsm4(bfr[2*p][0],bfr[2*p][1],bfr[2*p+1][0],bfr[2*p+1][1],
                  sbV + b_lane[p] + koff);
#pragma unroll
        for (int nf=0;nf<4;nf++) mma_f16(acc2[nf], a, bfr[nf]);
    }
#pragma unroll
    for (int ks=0; ks<4; ks++){
        uint32_t koff = (uint32_t)(ks*32);
        uint32_t a[4];
        ldsm4(a[0],a[1],a[2],a[3], sbQ + a_lane + koff);
        uint32_t bfr[4][2];
#pragma unroll
        for (int p=0;p<2;p++)
            ldsm4(bfr[2*p][0],bfr[2*p][1],bfr[2*p+1][0],bfr[2*p+1][1],
                  sbSt + b_lane[p] + koff);
#pragma unroll
        for (int nf=0;nf<4;nf++) mma_f16(acc2[nf], a, bfr[nf]);
    }

    float inv0 = 1.0f / dn[r0];
    float inv1 = 1.0f / dn[r1];
#pragma unroll
    for (int nf=0;nf<4;nf++){
        int col = nb + nf*8 + qp*2;
        size_t g0 = ((size_t)(b*TT + t0 + r0))*DM + h*DH + col;
        size_t g1 = ((size_t)(b*TT + t0 + r1))*DM + h*DH + col;
        *(uint32_t*)&attn1[g0] = pack2h(__float2half_rn(acc2[nf][0]*inv0),
                                        __float2half_rn(acc2[nf][1]*inv0));
        *(uint32_t*)&attn1[g1] = pack2h(__float2half_rn(acc2[nf][2]*inv1),
                                        __float2half_rn(acc2[nf][3]*inv1));
    }
}

// ---------------- launch ----------------
extern "C" void kernel_launch(void* const* d_in, const int* in_sizes, int n_in,
                              void* d_out, int out_size)
{
    (void)in_sizes; (void)n_in; (void)out_size;
    const float* x     = (const float*)d_in[0];
    const float* ln1_g = (const float*)d_in[1];
    const float* ln1_b = (const float*)d_in[2];
    const float* Wq    = (const float*)d_in[3];
    const float* bq    = (const float*)d_in[4];
    const float* Wk    = (const float*)d_in[5];
    const float* bk    = (const float*)d_in[6];
    const float* Wv    = (const float*)d_in[7];
    const float* bv    = (const float*)d_in[8];
    const float* Wo    = (const float*)d_in[9];
    const float* bo    = (const float*)d_in[10];
    const float* ln2_g = (const float*)d_in[11];
    const float* ln2_b = (const float*)d_in[12];
    const float* W1    = (const float*)d_in[13];
    const float* b1    = (const float*)d_in[14];
    const float* W2    = (const float*)d_in[15];
    const float* b2    = (const float*)d_in[16];
    float* out = (float*)d_out;

    static bool attr_done = false;
    if (!attr_done){
        cudaFuncSetAttribute(mm_kernel, cudaFuncAttributeMaxDynamicSharedMemorySize,
                             SMEM_MM);
        attr_done = true;
    }

    __half *h1b,*attn1b,*h22b,*ffn1b,*wqkvb,*wob,*w1b,*w2b,*qb,*kb,*vb,*Spb,*ckvb;
    float *x2b,*czb,*zpb;
    cudaGetSymbolAddress((void**)&h1b,   g_h1);
    cudaGetSymbolAddress((void**)&qb,    g_q);
    cudaGetSymbolAddress((void**)&kb,    g_k);
    cudaGetSymbolAddress((void**)&vb,    g_v);
    cudaGetSymbolAddress((void**)&attn1b,g_attn1);
    cudaGetSymbolAddress((void**)&x2b,   g_x2);
    cudaGetSymbolAddress((void**)&h22b,  g_h22);
    cudaGetSymbolAddress((void**)&ffn1b, g_ffn1);
    cudaGetSymbolAddress((void**)&wqkvb, g_wqkv);
    cudaGetSymbolAddress((void**)&wob,   g_wo);
    cudaGetSymbolAddress((void**)&w1b,   g_w1);
    cudaGetSymbolAddress((void**)&w2b,   g_w2);
    cudaGetSymbolAddress((void**)&ckvb,  g_ckv);
    cudaGetSymbolAddress((void**)&czb,   g_cz);
    cudaGetSymbolAddress((void**)&Spb,   g_Sp);
    cudaGetSymbolAddress((void**)&zpb,   g_zp);

    dim3 gQKV(3*DM/TN, MM/TM);      // (12, 32)
    dim3 gFF(DFF/TN, MM/TM);        // (16, 32)
    dim3 gDM(DM/TN, MM/TM);         // (4, 32)

    // sublayer 1 (LN1 + weight conversion fused into one launch)
    pre_kernel<<<MM + 1536, 256>>>(x, ln1_g, ln1_b, h1b,
                                   Wq, Wk, Wv, Wo, W1, W2,
                                   wqkvb, wob, w1b, w2b);
    mm_kernel<<<gQKV, 256, SMEM_MM>>>(h1b, wqkvb, bq, bk, bv, nullptr,
                                      nullptr, qb, kb, vb, nullptr,
                                      DM, DM, 4);
    chunk_sums_kernel<<<BH*NC, 256>>>(kb, vb, ckvb, czb);
    scan_kernel<<<BH*32, 256>>>(ckvb, czb, Spb, zpb);
    intra_kernel<<<BH*NC, 256>>>(qb, kb, vb, Spb, zpb, attn1b);
    mm_kernel<<<gDM, 256, SMEM_MM>>>(attn1b, wob, bo, nullptr, nullptr, x,
                                     x2b, nullptr, nullptr, nullptr, nullptr,
                                     DM, DM, 2);
    lnh_kernel<<<MM, 256>>>(x2b, ln2_g, ln2_b, h22b);

    // sublayer 2
    mm_kernel<<<gFF, 256, SMEM_MM>>>(h22b, w1b, b1, nullptr, nullptr, nullptr,
                                     nullptr, nullptr, nullptr, nullptr, ffn1b,
                                     DFF, DM, 3);
    mm_kernel<<<gDM, 256, SMEM_MM>>>(ffn1b, w2b, b2, nullptr, nullptr, x2b,
                                     out, nullptr, nullptr, nullptr, nullptr,
                                     DM, DFF, 2);
}